// round 11
// baseline (speedup 1.0000x reference)
#include <cuda_runtime.h>
#include <cstdint>

// TNorm: out[b, ((i0*8+i1)*8+i2)*8+i3] = g0[i0]*g1[i1]*g2[i2]*g3[i3], g=x[b].
// x: (16384,32) fp32 -> out: (16384,4096) fp32. 256 MiB pure write stream.
//
// Model (3x confirmed): plateau 45.3us = 512MB LTS transit (fill+drain) at
// the ~11.8TB/s LTS cap. createpolicy no_allocate doesn't compile (R9).
// R10: dual path with WRITE-THROUGH stg slice — chunks 6,7 (25%) stored via
// __stwt (st.global.wt.v4): write-through leaves no dirty L2 line -> those
// bytes transit LTS once. Chunks 0..5 via smem+TMA evict_first as before.

#define BATCH       16384
#define ROW_FLOATS  4096
#define TMA_CHUNKS  6
#define TMA_FLOATS  (TMA_CHUNKS * 512)         /* 3072 */
#define TMA_BYTES   (TMA_FLOATS * 4)           /* 12KB */
#define NT          128
#define NBUF        3
#define GRID_CTAS   (148 * 5)
#define SMEM_BYTES  (NBUF * TMA_BYTES + 2 * 32 * 4)

__global__ __launch_bounds__(NT)
void tnorm_wt_kernel(const float* __restrict__ x, float* __restrict__ out) {
    extern __shared__ float smem[];
    float* buf = smem;                        // NBUF x 3072 floats
    float* g   = smem + NBUF * TMA_FLOATS;    // 2 x 32 floats

    const int t = threadIdx.x;
    const int i1  = t >> 4;
    const int i2  = (t >> 1) & 7;
    const int i3b = (t & 1) * 4;

    uint64_t pol;
    asm volatile("createpolicy.fractional.L2::evict_first.b64 %0, 1.0;" : "=l"(pol));

    const int row0 = blockIdx.x;
    if (t < 8 && row0 < BATCH)
        reinterpret_cast<float4*>(g)[t] =
            reinterpret_cast<const float4*>(x + (size_t)row0 * 32)[t];
    __syncthreads();

    int it = 0;
    for (int row = row0; row < BATCH; row += gridDim.x, ++it) {
        float* b = buf + (it % NBUF) * TMA_FLOATS;
        const float* gc = g + (it & 1) * 32;

        if (t == 0)
            asm volatile("cp.async.bulk.wait_group.read 2;" ::: "memory");

        const int nrow = row + gridDim.x;
        if (t < 8 && nrow < BATCH)
            reinterpret_cast<float4*>(g + ((it + 1) & 1) * 32)[t] =
                reinterpret_cast<const float4*>(x + (size_t)nrow * 32)[t];

        __syncthreads();

        const float p12 = gc[8 + i1] * gc[16 + i2];
        const float4 a3 = *reinterpret_cast<const float4*>(&gc[24 + i3b]);
        float* orow = out + (size_t)row * ROW_FLOATS;

        // Write-through slice: chunks 6,7 (4KB/row, 64MB total) register-
        // direct, st.global.wt — no dirty L2 line, single LTS transit.
        #pragma unroll
        for (int k = TMA_CHUNKS; k < 8; k++) {
            const float s = gc[k] * p12;
            float4 v = make_float4(s * a3.x, s * a3.y, s * a3.z, s * a3.w);
            __stwt(reinterpret_cast<float4*>(orow + k * 512 + t * 4), v);
        }

        // TMA slice: chunks 0..5 into smem, one 12KB bulk store.
        #pragma unroll
        for (int k = 0; k < TMA_CHUNKS; k++) {
            const float s = gc[k] * p12;
            float4 v = make_float4(s * a3.x, s * a3.y, s * a3.z, s * a3.w);
            *reinterpret_cast<float4*>(b + k * 512 + t * 4) = v;
        }
        __syncthreads();

        if (t == 0) {
            asm volatile("fence.proxy.async.shared::cta;" ::: "memory");
            const uint32_t saddr = (uint32_t)__cvta_generic_to_shared(b);
            asm volatile(
                "cp.async.bulk.global.shared::cta.bulk_group.L2::cache_hint "
                "[%0], [%1], %2, %3;"
                :: "l"(orow), "r"(saddr), "n"(TMA_BYTES), "l"(pol) : "memory");
            asm volatile("cp.async.bulk.commit_group;" ::: "memory");
        }
    }

    if (t == 0)
        asm volatile("cp.async.bulk.wait_group.read 0;" ::: "memory");
    __syncthreads();
}

extern "C" void kernel_launch(void* const* d_in, const int* in_sizes, int n_in,
                              void* d_out, int out_size) {
    const float* x = (const float*)d_in[0];
    float* out = (float*)d_out;
    static bool attr_set = false;
    if (!attr_set) {
        cudaFuncSetAttribute(tnorm_wt_kernel,
                             cudaFuncAttributeMaxDynamicSharedMemorySize,
                             SMEM_BYTES);
        attr_set = true;
    }
    tnorm_wt_kernel<<<GRID_CTAS, NT, SMEM_BYTES>>>(x, out);
}

// round 12
// speedup vs baseline: 1.0544x; 1.0544x over previous
#include <cuda_runtime.h>
#include <cstdint>

// TNorm: out[b, ((i0*8+i1)*8+i2)*8+i3] = g0[i0]*g1[i1]*g2[i2]*g3[i3], g=x[b].
// x: (16384,32) fp32 -> out: (16384,4096) fp32. 256 MiB pure write stream.
//
// FINAL. Converged model (10 variants): every output byte transits LTS twice
// (SM->L2 fill + dirty drain), 512MB / ~11.8TB/s LTS cap -> ~43.5us floor.
// All bypasses closed by HW: no_allocate (no compile), .wt (demoted, -2us),
// evict_last retention (neutral/-2us), path superposition (neutral), issue
// shaping (neutral). Best measured: dual-path 12KB smem+TMA evict_first +
// 4KB register-direct __stcs per row. Re-bench of that variant.

#define BATCH       16384
#define ROW_FLOATS  4096
#define TMA_CHUNKS  6
#define TMA_FLOATS  (TMA_CHUNKS * 512)         /* 3072 */
#define TMA_BYTES   (TMA_FLOATS * 4)           /* 12KB */
#define NT          128
#define NBUF        3
#define GRID_CTAS   (148 * 5)
#define SMEM_BYTES  (NBUF * TMA_BYTES + 2 * 32 * 4)

__global__ __launch_bounds__(NT)
void tnorm_dual_kernel(const float* __restrict__ x, float* __restrict__ out) {
    extern __shared__ float smem[];
    float* buf = smem;                        // NBUF x 3072 floats
    float* g   = smem + NBUF * TMA_FLOATS;    // 2 x 32 floats

    const int t = threadIdx.x;
    const int i1  = t >> 4;
    const int i2  = (t >> 1) & 7;
    const int i3b = (t & 1) * 4;

    uint64_t pol;
    asm volatile("createpolicy.fractional.L2::evict_first.b64 %0, 1.0;" : "=l"(pol));

    const int row0 = blockIdx.x;
    if (t < 8 && row0 < BATCH)
        reinterpret_cast<float4*>(g)[t] =
            reinterpret_cast<const float4*>(x + (size_t)row0 * 32)[t];
    __syncthreads();

    int it = 0;
    for (int row = row0; row < BATCH; row += gridDim.x, ++it) {
        float* b = buf + (it % NBUF) * TMA_FLOATS;
        const float* gc = g + (it & 1) * 32;

        if (t == 0)
            asm volatile("cp.async.bulk.wait_group.read 2;" ::: "memory");

        const int nrow = row + gridDim.x;
        if (t < 8 && nrow < BATCH)
            reinterpret_cast<float4*>(g + ((it + 1) & 1) * 32)[t] =
                reinterpret_cast<const float4*>(x + (size_t)nrow * 32)[t];

        __syncthreads();

        const float p12 = gc[8 + i1] * gc[16 + i2];
        const float4 a3 = *reinterpret_cast<const float4*>(&gc[24 + i3b]);
        float* orow = out + (size_t)row * ROW_FLOATS;

        // STG slice: chunks 6,7 (4KB) register-direct streaming stores.
        #pragma unroll
        for (int k = TMA_CHUNKS; k < 8; k++) {
            const float s = gc[k] * p12;
            float4 v = make_float4(s * a3.x, s * a3.y, s * a3.z, s * a3.w);
            __stcs(reinterpret_cast<float4*>(orow + k * 512 + t * 4), v);
        }

        // TMA slice: chunks 0..5 into smem, one 12KB bulk store.
        #pragma unroll
        for (int k = 0; k < TMA_CHUNKS; k++) {
            const float s = gc[k] * p12;
            float4 v = make_float4(s * a3.x, s * a3.y, s * a3.z, s * a3.w);
            *reinterpret_cast<float4*>(b + k * 512 + t * 4) = v;
        }
        __syncthreads();

        if (t == 0) {
            asm volatile("fence.proxy.async.shared::cta;" ::: "memory");
            const uint32_t saddr = (uint32_t)__cvta_generic_to_shared(b);
            asm volatile(
                "cp.async.bulk.global.shared::cta.bulk_group.L2::cache_hint "
                "[%0], [%1], %2, %3;"
                :: "l"(orow), "r"(saddr), "n"(TMA_BYTES), "l"(pol) : "memory");
            asm volatile("cp.async.bulk.commit_group;" ::: "memory");
        }
    }

    if (t == 0)
        asm volatile("cp.async.bulk.wait_group.read 0;" ::: "memory");
    __syncthreads();
}

extern "C" void kernel_launch(void* const* d_in, const int* in_sizes, int n_in,
                              void* d_out, int out_size) {
    const float* x = (const float*)d_in[0];
    float* out = (float*)d_out;
    static bool attr_set = false;
    if (!attr_set) {
        cudaFuncSetAttribute(tnorm_dual_kernel,
                             cudaFuncAttributeMaxDynamicSharedMemorySize,
                             SMEM_BYTES);
        attr_set = true;
    }
    tnorm_dual_kernel<<<GRID_CTAS, NT, SMEM_BYTES>>>(x, out);
}